// round 15
// baseline (speedup 1.0000x reference)
#include <cuda_runtime.h>
#include <cuda_fp16.h>
#include <cstdint>

#define NN 20000
#define EE 320000
#define HH 280
#define GG 64
#define NFF 5
#define EFF 4
#define LL 3
#define ZZ 64
#define K_MSG 564   // 2H + EF
#define K_UPD 560   // 2H

// ---------------- scratch (static device globals; no runtime alloc) ----------------
__device__ float g_h[NN * HH];
__device__ float g_Y[EE * HH];
__device__ float g_agg[NN * HH];      // doubles as P2 during message phase
__device__ float g_U[NN * HH];        // doubles as P1 during message phase
__device__ float g_stats[2 * HH];
__device__ float g_scale[HH];
__device__ float g_shift[HH];
__device__ float g_pool[GG * HH];
__device__ float g_cnt[GG];
__device__ float g_zb[HH];            // zero bias
// pre-converted W images: per layer [wm1a:5][wm1b:5][wm2:5][wu1:9][wu2:5] = 29 chunks
__device__ uint32_t g_wb[LL * 29 * 9216];

// ================= helpers =================
__device__ __forceinline__ uint32_t smem_u32(const void* p) {
    uint32_t a;
    asm("{ .reg .u64 t; cvta.to.shared.u64 t, %1; cvt.u32.u64 %0, t; }" : "=r"(a) : "l"(p));
    return a;
}
#define SWZ(o) ((o) ^ (((o) >> 3) & 0x70))

__device__ __forceinline__ void ldsm_x4(uint32_t* r, uint32_t addr) {
    asm volatile("ldmatrix.sync.aligned.m8n8.x4.shared.b16 {%0,%1,%2,%3}, [%4];"
                 : "=r"(r[0]), "=r"(r[1]), "=r"(r[2]), "=r"(r[3]) : "r"(addr));
}
__device__ __forceinline__ void mma_f16(float* d, const uint32_t* a, uint32_t b0, uint32_t b1) {
    asm volatile("mma.sync.aligned.m16n8k16.row.col.f32.f16.f16.f32 "
                 "{%0,%1,%2,%3}, {%4,%5,%6,%7}, {%8,%9}, {%0,%1,%2,%3};"
                 : "+f"(d[0]), "+f"(d[1]), "+f"(d[2]), "+f"(d[3])
                 : "r"(a[0]), "r"(a[1]), "r"(a[2]), "r"(a[3]), "r"(b0), "r"(b1));
}

// smem layout (bytes) — generic GEMM: 52KB -> 3 blocks/SM
#define SM_STAT  0         // 560 floats (2240B)
#define SM_I0    2304      // 64 ints
#define SM_I1    2560
#define SM_SC    2816      // 280 floats
#define SM_SH    3936
#define SM_AH    8192      // 64x64 fp16 swizzled (8KB)
#define SM_BH    16384     // 288x64 fp16 swizzled (36KB)
#define SM_TOT   53248

// smem layout for fused message GEMM2 (56KB -> 3 blocks/SM)
#define F_STAT   0         // 2240B
#define F_I0     2304      // 64 ints
#define F_I1     2560
#define F_EV     2816      // 64 float4 (1024B)
#define F_W1C    3840      // 4*280 floats (4480B)
#define F_B1     8320      // 280 floats
#define F_SC     9472
#define F_SH     10624
#define F_AH     12288     // 8KB
#define F_BH     20480     // 36KB
#define F_TOT    57344

// ---------------- misc kernels ----------------
__global__ void zero4_kernel(float4* __restrict__ p, int n4) {
    int i = blockIdx.x * 256 + threadIdx.x;
    if (i < n4) p[i] = make_float4(0.f, 0.f, 0.f, 0.f);
}

__global__ void input_layer(const float* __restrict__ x, const float* __restrict__ Wi,
                            const float* __restrict__ bi, float* __restrict__ h) {
    int idx = blockIdx.x * 256 + threadIdx.x;
    if (idx >= NN * HH) return;
    int n = idx / HH;
    int c = idx - n * HH;
    float s = bi[c];
#pragma unroll
    for (int f = 0; f < NFF; f++) s = fmaf(x[n * NFF + f], Wi[f * HH + c], s);
    h[idx] = s;
}

// ---------------- W pre-conversion: fp32 [K,280] -> swizzled fp16 chunk image ----
__global__ void conv_w(const float* __restrict__ W, int K, int nCh,
                       uint32_t* __restrict__ ob) {
    int i = blockIdx.x * 256 + threadIdx.x;
    if (i >= nCh * 9216) return;
    int ch = i / 9216;
    int rem = i - ch * 9216;
    int kp = rem / 288;          // 0..31 (pair of k)
    int n = rem - kp * 288;      // 0..287
    int k0 = ch * 64 + 2 * kp;
    float v0 = (k0 < K && n < HH) ? W[(long)k0 * HH + n] : 0.f;
    float v1 = (k0 + 1 < K && n < HH) ? W[(long)(k0 + 1) * HH + n] : 0.f;
    __half2 hv = __floats2half2_rn(v0, v1);
    uint32_t off = SWZ((uint32_t)(n * 128 + kp * 4));
    ob[ch * 9216 + (off >> 2)] = *reinterpret_cast<uint32_t*>(&hv);
}

// ============================================================================
// HMMA compute core: one 64-k chunk, warp tile 16 rows x 144 cols, single fp16
// product. 8 warps: wm 0..3 (rows), wn 0..1 (cols). abase/bbase passed in.
// ============================================================================
__device__ __forceinline__ void hmma_chunk(uint32_t abase, uint32_t bbase, int wm, int wn,
                                           int lane, float acc[18][4]) {
#pragma unroll
    for (int ks = 0; ks < 4; ks++) {
        uint32_t ah[4];
        {
            int row = wm * 16 + (lane & 15);
            int koff = ks * 32 + ((lane >> 4) << 4);
            ldsm_x4(ah, abase + SWZ((uint32_t)(row * 128 + koff)));
        }
        int bkoff = ks * 32 + ((lane >> 3) & 1) * 16;
        int bn0 = wn * 144 + ((lane >> 4) << 3) + (lane & 7);
#pragma unroll
        for (int g = 0; g < 5; g++) {
            const int nta = 2 * g, ntb = 2 * g + 1;
            uint32_t ba[4], bb[4];
            ldsm_x4(ba, bbase + SWZ((uint32_t)((bn0 + nta * 16) * 128 + bkoff)));
            if (g < 4) ldsm_x4(bb, bbase + SWZ((uint32_t)((bn0 + ntb * 16) * 128 + bkoff)));
#pragma unroll
            for (int p = 0; p < 2; p++)
                mma_f16(acc[nta * 2 + p], ah, ba[2 * p], ba[2 * p + 1]);
            if (g < 4) {
#pragma unroll
                for (int p = 0; p < 2; p++)
                    mma_f16(acc[ntb * 2 + p], ah, bb[2 * p], bb[2 * p + 1]);
            }
        }
    }
}

// Epilogue: bias + guarded store + optional fused BN stats.
__device__ __forceinline__ void hmma_epilogue(float acc[18][4], long row0, int wm, int wn,
                                              int lane, const float* __restrict__ bias,
                                              float* __restrict__ Cout, float* sStat, int M,
                                              int doStat) {
    int rbase = wm * 16 + (lane >> 2);
    int cbase = wn * 144 + (lane & 3) * 2;
    long r1 = row0 + rbase;
    long r2 = r1 + 8;
    bool ok1 = r1 < M, ok2 = r2 < M;
#pragma unroll
    for (int nt = 0; nt < 18; nt++) {
        int c = cbase + nt * 8;
        if (c < HH) {
            float b0 = bias[c], b1 = bias[c + 1];
            float v0 = acc[nt][0] + b0;
            float v1 = acc[nt][1] + b1;
            float v2 = acc[nt][2] + b0;
            float v3 = acc[nt][3] + b1;
            float s0 = 0.f, s1 = 0.f, q0 = 0.f, q1 = 0.f;
            if (ok1) {
                *reinterpret_cast<float2*>(Cout + r1 * HH + c) = make_float2(v0, v1);
                s0 += v0; s1 += v1; q0 += v0 * v0; q1 += v1 * v1;
            }
            if (ok2) {
                *reinterpret_cast<float2*>(Cout + r2 * HH + c) = make_float2(v2, v3);
                s0 += v2; s1 += v3; q0 += v2 * v2; q1 += v3 * v3;
            }
            if (doStat && (ok1 || ok2)) {
                atomicAdd(&sStat[c], s0);
                atomicAdd(&sStat[c + 1], s1);
                atomicAdd(&sStat[HH + c], q0);
                atomicAdd(&sStat[HH + c + 1], q1);
            }
        }
    }
}

// ============================================================================
// Unified GEMM1: C[M,280] = cat(A0[idx0], A1[idx1], ea?) @ W[K,280] + b
// ============================================================================
__global__ void __launch_bounds__(256, 3)
gemm_cat_mma(const float* __restrict__ A0, const int* __restrict__ idx0,
             const float* __restrict__ A1, const int* __restrict__ idx1,
             const float* __restrict__ ea,
             const uint32_t* __restrict__ wb,
             const float* __restrict__ bias, float* __restrict__ Cout,
             int M, int K, int nCh, int doStat) {
    extern __shared__ char sm[];
    uint32_t sb = smem_u32(sm);
    const int tid = threadIdx.x, wid = tid >> 5, lane = tid & 31;
    const int wm = wid >> 1, wn = wid & 1;
    const long row0 = (long)blockIdx.x * 64;
    int* sI0 = (int*)(sm + SM_I0);
    int* sI1 = (int*)(sm + SM_I1);
    float* sStat = (float*)(sm + SM_STAT);

    for (int i = tid; i < 2 * HH; i += 256) sStat[i] = 0.f;
    if (tid < 64) {
        int e = (int)min(row0 + tid, (long)M - 1);
        sI0[tid] = idx0 ? idx0[e] : e;
        sI1[tid] = idx1 ? idx1[e] : e;
    }
    float acc[18][4];
#pragma unroll
    for (int nt = 0; nt < 18; nt++)
#pragma unroll
        for (int j = 0; j < 4; j++) acc[nt][j] = 0.f;
    __syncthreads();

    for (int ch = 0; ch < nCh; ++ch) {
        if (ch) __syncthreads();
        const int kbase = ch * 64;
        for (int i = tid; i < 2048; i += 256) {
            int r = i >> 5, kp = i & 31;
            int c = kbase + 2 * kp;
            float2 v = make_float2(0.f, 0.f);
            if (c < K) {
                if (c < HH)          v = *(const float2*)(A0 + (long)sI0[r] * HH + c);
                else if (c < 2 * HH) v = *(const float2*)(A1 + (long)sI1[r] * HH + (c - HH));
                else                 v = *(const float2*)(ea + (row0 + r) * EFF + (c - 2 * HH));
            }
            __half2 hv = __floats2half2_rn(v.x, v.y);
            uint32_t off = SWZ((uint32_t)(r * 128 + kp * 4));
            *(uint32_t*)(sm + SM_AH + off) = *reinterpret_cast<uint32_t*>(&hv);
        }
        {
            const float4* s1 = (const float4*)(wb + ch * 9216);
            float4* d1 = (float4*)(sm + SM_BH);
            for (int i = tid; i < 2304; i += 256) d1[i] = s1[i];
        }
        __syncthreads();
        hmma_chunk(sb + SM_AH, sb + SM_BH, wm, wn, lane, acc);
    }

    hmma_epilogue(acc, row0, wm, wn, lane, bias, Cout, sStat, M, doStat);
    if (doStat) {
        __syncthreads();
        for (int i = tid; i < 2 * HH; i += 256) atomicAdd(&g_stats[i], sStat[i]);
    }
}

// ============================================================================
// Unified GEMM2 (in place, node path): C[M,280] = relu(bn(C)) @ W[280,280] + b
// ============================================================================
__global__ void __launch_bounds__(256, 3)
gemm_inplace_mma(float* __restrict__ C, const uint32_t* __restrict__ wb,
                 const float* __restrict__ bias, int M) {
    extern __shared__ char sm[];
    uint32_t sb = smem_u32(sm);
    const int tid = threadIdx.x, wid = tid >> 5, lane = tid & 31;
    const int wm = wid >> 1, wn = wid & 1;
    const long row0 = (long)blockIdx.x * 64;
    float* sStat = (float*)(sm + SM_STAT);
    float* sSc = (float*)(sm + SM_SC);
    float* sSh = (float*)(sm + SM_SH);

    for (int i = tid; i < 2 * HH; i += 256) sStat[i] = 0.f;
    for (int i = tid; i < HH; i += 256) { sSc[i] = g_scale[i]; sSh[i] = g_shift[i]; }
    float acc[18][4];
#pragma unroll
    for (int nt = 0; nt < 18; nt++)
#pragma unroll
        for (int j = 0; j < 4; j++) acc[nt][j] = 0.f;
    __syncthreads();

    for (int ch = 0; ch < 5; ++ch) {
        if (ch) __syncthreads();
        const int kbase = ch * 64;
        for (int i = tid; i < 2048; i += 256) {
            int r = i >> 5, kp = i & 31;
            int c = kbase + 2 * kp;
            float2 v = make_float2(0.f, 0.f);
            if (c < HH) {
                long row = min(row0 + r, (long)M - 1);
                float2 y = *(const float2*)(C + row * HH + c);
                v.x = fmaxf(fmaf(y.x, sSc[c], sSh[c]), 0.f);
                v.y = fmaxf(fmaf(y.y, sSc[c + 1], sSh[c + 1]), 0.f);
            }
            __half2 hv = __floats2half2_rn(v.x, v.y);
            uint32_t off = SWZ((uint32_t)(r * 128 + kp * 4));
            *(uint32_t*)(sm + SM_AH + off) = *reinterpret_cast<uint32_t*>(&hv);
        }
        {
            const float4* s1 = (const float4*)(wb + ch * 9216);
            float4* d1 = (float4*)(sm + SM_BH);
            for (int i = tid; i < 2304; i += 256) d1[i] = s1[i];
        }
        __syncthreads();
        hmma_chunk(sb + SM_AH, sb + SM_BH, wm, wn, lane, acc);
    }

    hmma_epilogue(acc, row0, wm, wn, lane, bias, C, sStat, M, 1);
    __syncthreads();
    for (int i = tid; i < 2 * HH; i += 256) atomicAdd(&g_stats[i], sStat[i]);
}

// ============================================================================
// Fused message GEMM2: Y = relu(bn1(P1[dst]+P2[src]+ea@W1c+b1)) @ W2 + b2
// Message computed on the fly from L2-resident P1/P2 — no Y round trip.
// ============================================================================
__global__ void __launch_bounds__(256, 3)
gemm2_fused(const float* __restrict__ P1, const float* __restrict__ P2,
            const float* __restrict__ ea,
            const int* __restrict__ dst, const int* __restrict__ src,
            const float* __restrict__ W1c, const float* __restrict__ b1,
            const uint32_t* __restrict__ wb, const float* __restrict__ b2,
            float* __restrict__ Y) {
    extern __shared__ char sm[];
    uint32_t sb = smem_u32(sm);
    const int tid = threadIdx.x, wid = tid >> 5, lane = tid & 31;
    const int wm = wid >> 1, wn = wid & 1;
    const long row0 = (long)blockIdx.x * 64;
    int* sI0 = (int*)(sm + F_I0);
    int* sI1 = (int*)(sm + F_I1);
    float4* sEv = (float4*)(sm + F_EV);
    float* sW1c = (float*)(sm + F_W1C);
    float* sB1 = (float*)(sm + F_B1);
    float* sSc = (float*)(sm + F_SC);
    float* sSh = (float*)(sm + F_SH);
    float* sStat = (float*)(sm + F_STAT);

    for (int i = tid; i < 2 * HH; i += 256) sStat[i] = 0.f;
    for (int i = tid; i < EFF * HH; i += 256) sW1c[i] = W1c[i];
    for (int i = tid; i < HH; i += 256) {
        sB1[i] = b1[i];
        sSc[i] = g_scale[i];
        sSh[i] = g_shift[i];
    }
    if (tid < 64) {
        long e = row0 + tid;
        sI0[tid] = dst[e];
        sI1[tid] = src[e];
        sEv[tid] = *(const float4*)(ea + e * EFF);
    }
    float acc[18][4];
#pragma unroll
    for (int nt = 0; nt < 18; nt++)
#pragma unroll
        for (int j = 0; j < 4; j++) acc[nt][j] = 0.f;
    __syncthreads();

    for (int ch = 0; ch < 5; ++ch) {
        if (ch) __syncthreads();
        const int kbase = ch * 64;
        for (int i = tid; i < 2048; i += 256) {
            int r = i >> 5, kp = i & 31;
            int c = kbase + 2 * kp;
            float2 v = make_float2(0.f, 0.f);
            if (c < HH) {
                float2 a = *(const float2*)(P1 + (long)sI0[r] * HH + c);
                float2 b = *(const float2*)(P2 + (long)sI1[r] * HH + c);
                float4 evv = sEv[r];
                float m0 = a.x + b.x + sB1[c] +
                           evv.x * sW1c[c] + evv.y * sW1c[HH + c] +
                           evv.z * sW1c[2 * HH + c] + evv.w * sW1c[3 * HH + c];
                float m1 = a.y + b.y + sB1[c + 1] +
                           evv.x * sW1c[c + 1] + evv.y * sW1c[HH + c + 1] +
                           evv.z * sW1c[2 * HH + c + 1] + evv.w * sW1c[3 * HH + c + 1];
                v.x = fmaxf(fmaf(m0, sSc[c], sSh[c]), 0.f);
                v.y = fmaxf(fmaf(m1, sSc[c + 1], sSh[c + 1]), 0.f);
            }
            __half2 hv = __floats2half2_rn(v.x, v.y);
            uint32_t off = SWZ((uint32_t)(r * 128 + kp * 4));
            *(uint32_t*)(sm + F_AH + off) = *reinterpret_cast<uint32_t*>(&hv);
        }
        {
            const float4* s1 = (const float4*)(wb + ch * 9216);
            float4* d1 = (float4*)(sm + F_BH);
            for (int i = tid; i < 2304; i += 256) d1[i] = s1[i];
        }
        __syncthreads();
        hmma_chunk(sb + F_AH, sb + F_BH, wm, wn, lane, acc);
    }

    hmma_epilogue(acc, row0, wm, wn, lane, b2, Y, sStat, EE, 1);
    __syncthreads();
    for (int i = tid; i < 2 * HH; i += 256) atomicAdd(&g_stats[i], sStat[i]);
}

// ============================================================================
// stats_msg: BN1 stats of m[e] = P1[dst]+P2[src]+ea@W1c+b1 (no Y store)
// ============================================================================
__global__ void __launch_bounds__(256)
stats_msg(const float* __restrict__ P1, const float* __restrict__ P2,
          const float* __restrict__ ea,
          const int* __restrict__ dst, const int* __restrict__ src,
          const float* __restrict__ W1c, const float* __restrict__ bias) {
    __shared__ float sStat[2 * HH];
    __shared__ float sW[EFF * HH];
    __shared__ float sB[HH];
    __shared__ int sD[32], sS[32];
    __shared__ float4 sEv[32];
    const int tid = threadIdx.x;
    const long e0 = (long)blockIdx.x * 32;

    for (int i = tid; i < 2 * HH; i += 256) sStat[i] = 0.f;
    for (int i = tid; i < EFF * HH; i += 256) sW[i] = W1c[i];
    for (int i = tid; i < HH; i += 256) sB[i] = bias[i];
    if (tid < 32) {
        long e = e0 + tid;
        sD[tid] = dst[e];
        sS[tid] = src[e];
        sEv[tid] = *(const float4*)(ea + e * EFF);
    }
    __syncthreads();

    for (int it = tid; it < 32 * 70; it += 256) {
        int er = it / 70, c4 = it - er * 70;
        int c = c4 * 4;
        float4 a = *(const float4*)(P1 + (long)sD[er] * HH + c);
        float4 b = *(const float4*)(P2 + (long)sS[er] * HH + c);
        float4 ev = sEv[er];
        float v0 = a.x + b.x + sB[c + 0] + ev.x * sW[c + 0] + ev.y * sW[HH + c + 0] + ev.z * sW[2 * HH + c + 0] + ev.w * sW[3 * HH + c + 0];
        float v1 = a.y + b.y + sB[c + 1] + ev.x * sW[c + 1] + ev.y * sW[HH + c + 1] + ev.z * sW[2 * HH + c + 1] + ev.w * sW[3 * HH + c + 1];
        float v2 = a.z + b.z + sB[c + 2] + ev.x * sW[c + 2] + ev.y * sW[HH + c + 2] + ev.z * sW[2 * HH + c + 2] + ev.w * sW[3 * HH + c + 2];
        float v3 = a.w + b.w + sB[c + 3] + ev.x * sW[c + 3] + ev.y * sW[HH + c + 3] + ev.z * sW[2 * HH + c + 3] + ev.w * sW[3 * HH + c + 3];
        atomicAdd(&sStat[c + 0], v0);
        atomicAdd(&sStat[c + 1], v1);
        atomicAdd(&sStat[c + 2], v2);
        atomicAdd(&sStat[c + 3], v3);
        atomicAdd(&sStat[HH + c + 0], v0 * v0);
        atomicAdd(&sStat[HH + c + 1], v1 * v1);
        atomicAdd(&sStat[HH + c + 2], v2 * v2);
        atomicAdd(&sStat[HH + c + 3], v3 * v3);
    }
    __syncthreads();
    for (int i = tid; i < 2 * HH; i += 256) atomicAdd(&g_stats[i], sStat[i]);
}

// ---------------- finalize BN stats -> scale/shift; self-zero ----------------
__global__ void finalize_stats(const float* __restrict__ g, const float* __restrict__ be,
                               float invM) {
    int c = threadIdx.x;
    if (c >= HH) return;
    float s = g_stats[c];
    float s2 = g_stats[HH + c];
    g_stats[c] = 0.f;
    g_stats[HH + c] = 0.f;
    float mean = s * invM;
    float var = s2 * invM - mean * mean;
    float rstd = rsqrtf(var + 1e-5f);
    float sc = g[c] * rstd;
    g_scale[c] = sc;
    g_shift[c] = fmaf(-mean, sc, be[c]);
}

// ---------------- scatter: agg[dst[e]] += relu(bn(Y[e])) ----------------
__global__ void scatter_bn_relu(const float* __restrict__ Y, const int* __restrict__ dst,
                                float* __restrict__ agg) {
    long i = (long)blockIdx.x * 256 + threadIdx.x;
    if (i >= (long)EE * (HH / 4)) return;
    int e = (int)(i / (HH / 4));
    int c = (int)(i - (long)e * (HH / 4)) * 4;
    float4 y = *reinterpret_cast<const float4*>(Y + (long)e * HH + c);
    float* p = agg + (long)dst[e] * HH + c;
    float v0 = fmaf(y.x, g_scale[c + 0], g_shift[c + 0]);
    float v1 = fmaf(y.y, g_scale[c + 1], g_shift[c + 1]);
    float v2 = fmaf(y.z, g_scale[c + 2], g_shift[c + 2]);
    float v3 = fmaf(y.w, g_scale[c + 3], g_shift[c + 3]);
    if (v0 > 0.f) atomicAdd(p + 0, v0);
    if (v1 > 0.f) atomicAdd(p + 1, v1);
    if (v2 > 0.f) atomicAdd(p + 2, v2);
    if (v3 > 0.f) atomicAdd(p + 3, v3);
}

// ---------------- residual: h += relu(bn(U)) ----------------
__global__ void residual_bn_relu(const float* __restrict__ U, float* __restrict__ h) {
    int i = blockIdx.x * 256 + threadIdx.x;
    if (i >= NN * HH / 4) return;
    int c = (i % (HH / 4)) * 4;
    float4 u = *reinterpret_cast<const float4*>(U + (long)i * 4);
    float4 hv = *reinterpret_cast<float4*>(h + (long)i * 4);
    hv.x += fmaxf(fmaf(u.x, g_scale[c + 0], g_shift[c + 0]), 0.f);
    hv.y += fmaxf(fmaf(u.y, g_scale[c + 1], g_shift[c + 1]), 0.f);
    hv.z += fmaxf(fmaf(u.z, g_scale[c + 2], g_shift[c + 2]), 0.f);
    hv.w += fmaxf(fmaf(u.w, g_scale[c + 3], g_shift[c + 3]), 0.f);
    *reinterpret_cast<float4*>(h + (long)i * 4) = hv;
}

// ---------------- pooling + head ----------------
__global__ void pool_accum(const float* __restrict__ h, const int* __restrict__ batch,
                           float* __restrict__ pool) {
    int i = blockIdx.x * 256 + threadIdx.x;
    if (i >= NN * HH / 4) return;
    int n = i / (HH / 4);
    int c = (i - n * (HH / 4)) * 4;
    float4 v = *reinterpret_cast<const float4*>(h + (long)i * 4);
    float* p = pool + (long)batch[n] * HH + c;
    atomicAdd(p + 0, v.x);
    atomicAdd(p + 1, v.y);
    atomicAdd(p + 2, v.z);
    atomicAdd(p + 3, v.w);
}

__global__ void pool_count(const int* __restrict__ batch, float* __restrict__ cnt) {
    int n = blockIdx.x * 256 + threadIdx.x;
    if (n < NN) atomicAdd(&cnt[batch[n]], 1.0f);
}

__global__ void head_kernel(const float* __restrict__ pool, const float* __restrict__ cnt,
                            const float* __restrict__ Wmu, const float* __restrict__ bmu,
                            float* __restrict__ out) {
    int gph = blockIdx.x;
    int z = threadIdx.x;
    float inv = 1.0f / fmaxf(cnt[gph], 1.0f);
    float s = bmu[z];
    for (int k = 0; k < HH; k++) s = fmaf(pool[gph * HH + k] * inv, Wmu[k * ZZ + z], s);
    out[gph * ZZ + z] = s;
}

// ---------------- host orchestration ----------------
extern "C" void kernel_launch(void* const* d_in, const int* in_sizes, int n_in,
                              void* d_out, int out_size) {
    const float *x, *edge_attr, *Wi, *bi, *Wm1, *bm1, *g1, *be1, *Wm2, *bm2, *g2, *be2;
    const float *Wu1, *bu1, *g3, *be3, *Wu2, *bu2, *g4, *be4, *Wmu, *bmu;
    const int *edge_index, *batch;

    if (in_sizes[2] == 2 * EE) {
        x = (const float*)d_in[0];   edge_attr = (const float*)d_in[1];
        edge_index = (const int*)d_in[2]; batch = (const int*)d_in[3];
        Wi = (const float*)d_in[4];  bi = (const float*)d_in[5];
        Wm1 = (const float*)d_in[6]; bm1 = (const float*)d_in[7];
        g1 = (const float*)d_in[8];  be1 = (const float*)d_in[9];
        Wm2 = (const float*)d_in[10]; bm2 = (const float*)d_in[11];
        g2 = (const float*)d_in[12]; be2 = (const float*)d_in[13];
        Wu1 = (const float*)d_in[14]; bu1 = (const float*)d_in[15];
        g3 = (const float*)d_in[16]; be3 = (const float*)d_in[17];
        Wu2 = (const float*)d_in[18]; bu2 = (const float*)d_in[19];
        g4 = (const float*)d_in[20]; be4 = (const float*)d_in[21];
        Wmu = (const float*)d_in[22]; bmu = (const float*)d_in[23];
    } else {
        x = (const float*)d_in[0];   edge_attr = (const float*)d_in[1];
        Wi = (const float*)d_in[2];  bi = (const float*)d_in[3];
        Wm1 = (const float*)d_in[4]; bm1 = (const float*)d_in[5];
        g1 = (const float*)d_in[6];  be1 = (const float*)d_in[7];
        Wm2 = (const float*)d_in[8]; bm2 = (const float*)d_in[9];
        g2 = (const float*)d_in[10]; be2 = (const float*)d_in[11];
        Wu1 = (const float*)d_in[12]; bu1 = (const float*)d_in[13];
        g3 = (const float*)d_in[14]; be3 = (const float*)d_in[15];
        Wu2 = (const float*)d_in[16]; bu2 = (const float*)d_in[17];
        g4 = (const float*)d_in[18]; be4 = (const float*)d_in[19];
        Wmu = (const float*)d_in[20]; bmu = (const float*)d_in[21];
        edge_index = (const int*)d_in[22]; batch = (const int*)d_in[23];
    }
    const int* src = edge_index;
    const int* dst = edge_index + EE;

    float *hbuf, *Ybuf, *aggbuf, *Ubuf, *poolbuf, *cntbuf, *statsbuf, *zbuf;
    uint32_t *wb;
    cudaGetSymbolAddress((void**)&hbuf, g_h);
    cudaGetSymbolAddress((void**)&Ybuf, g_Y);
    cudaGetSymbolAddress((void**)&aggbuf, g_agg);
    cudaGetSymbolAddress((void**)&Ubuf, g_U);
    cudaGetSymbolAddress((void**)&poolbuf, g_pool);
    cudaGetSymbolAddress((void**)&cntbuf, g_cnt);
    cudaGetSymbolAddress((void**)&statsbuf, g_stats);
    cudaGetSymbolAddress((void**)&zbuf, g_zb);
    cudaGetSymbolAddress((void**)&wb, g_wb);

    cudaFuncSetAttribute(gemm_cat_mma, cudaFuncAttributeMaxDynamicSharedMemorySize, SM_TOT);
    cudaFuncSetAttribute(gemm_inplace_mma, cudaFuncAttributeMaxDynamicSharedMemorySize, SM_TOT);
    cudaFuncSetAttribute(gemm2_fused, cudaFuncAttributeMaxDynamicSharedMemorySize, F_TOT);

    const int NH_BLKS = (NN * HH + 255) / 256;
    const int NH4_BLKS = (NN * HH / 4 + 255) / 256;
    const int MSG_BLKS = EE / 64;                     // 5000
    const int UPD_BLKS = (NN + 63) / 64;              // 313
    const long EH4 = (long)EE * (HH / 4);
    const int SC_BLKS = (int)((EH4 + 255) / 256);

    zero4_kernel<<<1, 256>>>((float4*)statsbuf, 2 * HH / 4);
    zero4_kernel<<<1, 256>>>((float4*)zbuf, HH / 4);
    input_layer<<<NH_BLKS, 256>>>(x, Wi, bi, hbuf);

    // ---- pre-convert ALL weight images ----
    for (int l = 0; l < LL; l++) {
        uint32_t* base = wb + (long)l * 29 * 9216;
        const float* wm1 = Wm1 + (long)l * K_MSG * HH;
        conv_w<<<(5 * 9216) / 256, 256>>>(wm1, HH, 5, base);                       // W1a
        conv_w<<<(5 * 9216) / 256, 256>>>(wm1 + 280 * HH, HH, 5, base + 5 * 9216); // W1b
        conv_w<<<(5 * 9216) / 256, 256>>>(Wm2 + (long)l * HH * HH, HH, 5, base + 10 * 9216);
        conv_w<<<(9 * 9216) / 256, 256>>>(Wu1 + (long)l * K_UPD * HH, K_UPD, 9, base + 15 * 9216);
        conv_w<<<(5 * 9216) / 256, 256>>>(Wu2 + (long)l * HH * HH, HH, 5, base + 24 * 9216);
    }

    for (int l = 0; l < LL; l++) {
        uint32_t* wbase = wb + (long)l * 29 * 9216;
        const float* wm1 = Wm1 + (long)l * K_MSG * HH;
        const float* w1c = wm1 + 560 * HH;

        // ---- message MLP: P1=h@W1a, P2=h@W1b, stats, fused GEMM2 ----
        gemm_cat_mma<<<UPD_BLKS, 256, SM_TOT>>>(hbuf, nullptr, hbuf, nullptr, nullptr,
                                                wbase, zbuf, Ubuf /*P1*/, NN, HH, 5, 0);
        gemm_cat_mma<<<UPD_BLKS, 256, SM_TOT>>>(hbuf, nullptr, hbuf, nullptr, nullptr,
                                                wbase + 5 * 9216, zbuf, aggbuf /*P2*/, NN, HH, 5, 0);
        stats_msg<<<EE / 32, 256>>>(Ubuf, aggbuf, edge_attr, dst, src, w1c, bm1 + l * HH);
        finalize_stats<<<1, 288>>>(g1 + l * HH, be1 + l * HH, 1.0f / EE);
        gemm2_fused<<<MSG_BLKS, 256, F_TOT>>>(Ubuf, aggbuf, edge_attr, dst, src,
                                              w1c, bm1 + l * HH,
                                              wbase + 10 * 9216, bm2 + l * HH, Ybuf);
        finalize_stats<<<1, 288>>>(g2 + l * HH, be2 + l * HH, 1.0f / EE);

        // ---- aggregate ----
        zero4_kernel<<<NH4_BLKS, 256>>>((float4*)aggbuf, NN * HH / 4);
        scatter_bn_relu<<<SC_BLKS, 256>>>(Ybuf, dst, aggbuf);

        // ---- update MLP on nodes ----
        gemm_cat_mma<<<UPD_BLKS, 256, SM_TOT>>>(hbuf, nullptr, aggbuf, nullptr, nullptr,
                                                wbase + 15 * 9216, bu1 + l * HH, Ubuf, NN, K_UPD, 9, 1);
        finalize_stats<<<1, 288>>>(g3 + l * HH, be3 + l * HH, 1.0f / NN);
        gemm_inplace_mma<<<UPD_BLKS, 256, SM_TOT>>>(Ubuf, wbase + 24 * 9216, bu2 + l * HH, NN);
        finalize_stats<<<1, 288>>>(g4 + l * HH, be4 + l * HH, 1.0f / NN);
        residual_bn_relu<<<NH4_BLKS, 256>>>(Ubuf, hbuf);
    }

    zero4_kernel<<<(GG * HH / 4 + 255) / 256, 256>>>((float4*)poolbuf, GG * HH / 4);
    zero4_kernel<<<1, 256>>>((float4*)cntbuf, GG / 4);
    pool_accum<<<NH4_BLKS, 256>>>(hbuf, batch, poolbuf);
    pool_count<<<(NN + 255) / 256, 256>>>(batch, cntbuf);
    head_kernel<<<GG, ZZ>>>(poolbuf, cntbuf, Wmu, bmu, (float*)d_out);
}

// round 16
// speedup vs baseline: 1.1617x; 1.1617x over previous
#include <cuda_runtime.h>
#include <cuda_fp16.h>
#include <cstdint>

#define NN 20000
#define EE 320000
#define HH 280
#define GG 64
#define NFF 5
#define EFF 4
#define LL 3
#define ZZ 64
#define K_MSG 564   // 2H + EF
#define K_UPD 560   // 2H
#define ETILES (EE / 64)   // 5000

// ---------------- scratch (static device globals; no runtime alloc) ----------------
__device__ float g_h[NN * HH];
__device__ float g_Y[EE * HH];
__device__ float g_agg[NN * HH];      // doubles as P2 during message phase
__device__ float g_U[NN * HH];        // doubles as P1 during message phase
__device__ float g_stats[2 * HH];
__device__ float g_scale[HH];
__device__ float g_shift[HH];
__device__ float g_pool[GG * HH];
__device__ float g_cnt[GG];
__device__ float g_zb[HH];            // zero bias
// m stored as pre-swizzled fp16 chunk images: [tile][5 chunks][2048 u32]
__device__ uint32_t g_mf[(long)ETILES * 5 * 2048];
// pre-converted W images: per layer [wm1a:5][wm1b:5][wm2:5][wu1:9][wu2:5] = 29 chunks
__device__ uint32_t g_wb[LL * 29 * 9216];

// ================= helpers =================
__device__ __forceinline__ uint32_t smem_u32(const void* p) {
    uint32_t a;
    asm("{ .reg .u64 t; cvta.to.shared.u64 t, %1; cvt.u32.u64 %0, t; }" : "=r"(a) : "l"(p));
    return a;
}
#define SWZ(o) ((o) ^ (((o) >> 3) & 0x70))

__device__ __forceinline__ void ldsm_x4(uint32_t* r, uint32_t addr) {
    asm volatile("ldmatrix.sync.aligned.m8n8.x4.shared.b16 {%0,%1,%2,%3}, [%4];"
                 : "=r"(r[0]), "=r"(r[1]), "=r"(r[2]), "=r"(r[3]) : "r"(addr));
}
__device__ __forceinline__ void mma_f16(float* d, const uint32_t* a, uint32_t b0, uint32_t b1) {
    asm volatile("mma.sync.aligned.m16n8k16.row.col.f32.f16.f16.f32 "
                 "{%0,%1,%2,%3}, {%4,%5,%6,%7}, {%8,%9}, {%0,%1,%2,%3};"
                 : "+f"(d[0]), "+f"(d[1]), "+f"(d[2]), "+f"(d[3])
                 : "r"(a[0]), "r"(a[1]), "r"(a[2]), "r"(a[3]), "r"(b0), "r"(b1));
}

// smem layout (bytes) — generic GEMM: 52KB -> 3 blocks/SM
#define SM_STAT  0         // 560 floats (2240B)
#define SM_I0    2304      // 64 ints
#define SM_I1    2560
#define SM_SC    2816      // 280 floats
#define SM_SH    3936
#define SM_AH    8192      // 64x64 fp16 swizzled (8KB)
#define SM_BH    16384     // 288x64 fp16 swizzled (36KB)
#define SM_TOT   53248

// ---------------- misc kernels ----------------
__global__ void zero4_kernel(float4* __restrict__ p, int n4) {
    int i = blockIdx.x * 256 + threadIdx.x;
    if (i < n4) p[i] = make_float4(0.f, 0.f, 0.f, 0.f);
}

__global__ void input_layer(const float* __restrict__ x, const float* __restrict__ Wi,
                            const float* __restrict__ bi, float* __restrict__ h) {
    int idx = blockIdx.x * 256 + threadIdx.x;
    if (idx >= NN * HH) return;
    int n = idx / HH;
    int c = idx - n * HH;
    float s = bi[c];
#pragma unroll
    for (int f = 0; f < NFF; f++) s = fmaf(x[n * NFF + f], Wi[f * HH + c], s);
    h[idx] = s;
}

// ---------------- W pre-conversion: fp32 [K,280] -> swizzled fp16 chunk image ----
__global__ void conv_w(const float* __restrict__ W, int K, int nCh,
                       uint32_t* __restrict__ ob) {
    int i = blockIdx.x * 256 + threadIdx.x;
    if (i >= nCh * 9216) return;
    int ch = i / 9216;
    int rem = i - ch * 9216;
    int kp = rem / 288;          // 0..31 (pair of k)
    int n = rem - kp * 288;      // 0..287
    int k0 = ch * 64 + 2 * kp;
    float v0 = (k0 < K && n < HH) ? W[(long)k0 * HH + n] : 0.f;
    float v1 = (k0 + 1 < K && n < HH) ? W[(long)(k0 + 1) * HH + n] : 0.f;
    __half2 hv = __floats2half2_rn(v0, v1);
    uint32_t off = SWZ((uint32_t)(n * 128 + kp * 4));
    ob[ch * 9216 + (off >> 2)] = *reinterpret_cast<uint32_t*>(&hv);
}

// ============================================================================
// HMMA compute core: one 64-k chunk, warp tile 16 rows x 144 cols, single fp16
// product. 8 warps: wm 0..3 (rows), wn 0..1 (cols).
// ============================================================================
__device__ __forceinline__ void hmma_chunk(uint32_t abase, uint32_t bbase, int wm, int wn,
                                           int lane, float acc[18][4]) {
#pragma unroll
    for (int ks = 0; ks < 4; ks++) {
        uint32_t ah[4];
        {
            int row = wm * 16 + (lane & 15);
            int koff = ks * 32 + ((lane >> 4) << 4);
            ldsm_x4(ah, abase + SWZ((uint32_t)(row * 128 + koff)));
        }
        int bkoff = ks * 32 + ((lane >> 3) & 1) * 16;
        int bn0 = wn * 144 + ((lane >> 4) << 3) + (lane & 7);
#pragma unroll
        for (int g = 0; g < 5; g++) {
            const int nta = 2 * g, ntb = 2 * g + 1;
            uint32_t ba[4], bb[4];
            ldsm_x4(ba, bbase + SWZ((uint32_t)((bn0 + nta * 16) * 128 + bkoff)));
            if (g < 4) ldsm_x4(bb, bbase + SWZ((uint32_t)((bn0 + ntb * 16) * 128 + bkoff)));
#pragma unroll
            for (int p = 0; p < 2; p++)
                mma_f16(acc[nta * 2 + p], ah, ba[2 * p], ba[2 * p + 1]);
            if (g < 4) {
#pragma unroll
                for (int p = 0; p < 2; p++)
                    mma_f16(acc[ntb * 2 + p], ah, bb[2 * p], bb[2 * p + 1]);
            }
        }
    }
}

// Epilogue: bias + guarded store + optional fused BN stats.
__device__ __forceinline__ void hmma_epilogue(float acc[18][4], long row0, int wm, int wn,
                                              int lane, const float* __restrict__ bias,
                                              float* __restrict__ Cout, float* sStat, int M,
                                              int doStat) {
    int rbase = wm * 16 + (lane >> 2);
    int cbase = wn * 144 + (lane & 3) * 2;
    long r1 = row0 + rbase;
    long r2 = r1 + 8;
    bool ok1 = r1 < M, ok2 = r2 < M;
#pragma unroll
    for (int nt = 0; nt < 18; nt++) {
        int c = cbase + nt * 8;
        if (c < HH) {
            float b0 = bias[c], b1 = bias[c + 1];
            float v0 = acc[nt][0] + b0;
            float v1 = acc[nt][1] + b1;
            float v2 = acc[nt][2] + b0;
            float v3 = acc[nt][3] + b1;
            float s0 = 0.f, s1 = 0.f, q0 = 0.f, q1 = 0.f;
            if (ok1) {
                *reinterpret_cast<float2*>(Cout + r1 * HH + c) = make_float2(v0, v1);
                s0 += v0; s1 += v1; q0 += v0 * v0; q1 += v1 * v1;
            }
            if (ok2) {
                *reinterpret_cast<float2*>(Cout + r2 * HH + c) = make_float2(v2, v3);
                s0 += v2; s1 += v3; q0 += v2 * v2; q1 += v3 * v3;
            }
            if (doStat && (ok1 || ok2)) {
                atomicAdd(&sStat[c], s0);
                atomicAdd(&sStat[c + 1], s1);
                atomicAdd(&sStat[HH + c], q0);
                atomicAdd(&sStat[HH + c + 1], q1);
            }
        }
    }
}

// ============================================================================
// Unified GEMM1: C[M,280] = cat(A0[idx0], A1[idx1], ea?) @ W[K,280] + b
// ============================================================================
__global__ void __launch_bounds__(256, 3)
gemm_cat_mma(const float* __restrict__ A0, const int* __restrict__ idx0,
             const float* __restrict__ A1, const int* __restrict__ idx1,
             const float* __restrict__ ea,
             const uint32_t* __restrict__ wb,
             const float* __restrict__ bias, float* __restrict__ Cout,
             int M, int K, int nCh, int doStat) {
    extern __shared__ char sm[];
    uint32_t sb = smem_u32(sm);
    const int tid = threadIdx.x, wid = tid >> 5, lane = tid & 31;
    const int wm = wid >> 1, wn = wid & 1;
    const long row0 = (long)blockIdx.x * 64;
    int* sI0 = (int*)(sm + SM_I0);
    int* sI1 = (int*)(sm + SM_I1);
    float* sStat = (float*)(sm + SM_STAT);

    for (int i = tid; i < 2 * HH; i += 256) sStat[i] = 0.f;
    if (tid < 64) {
        int e = (int)min(row0 + tid, (long)M - 1);
        sI0[tid] = idx0 ? idx0[e] : e;
        sI1[tid] = idx1 ? idx1[e] : e;
    }
    float acc[18][4];
#pragma unroll
    for (int nt = 0; nt < 18; nt++)
#pragma unroll
        for (int j = 0; j < 4; j++) acc[nt][j] = 0.f;
    __syncthreads();

    for (int ch = 0; ch < nCh; ++ch) {
        if (ch) __syncthreads();
        const int kbase = ch * 64;
        for (int i = tid; i < 2048; i += 256) {
            int r = i >> 5, kp = i & 31;
            int c = kbase + 2 * kp;
            float2 v = make_float2(0.f, 0.f);
            if (c < K) {
                if (c < HH)          v = *(const float2*)(A0 + (long)sI0[r] * HH + c);
                else if (c < 2 * HH) v = *(const float2*)(A1 + (long)sI1[r] * HH + (c - HH));
                else                 v = *(const float2*)(ea + (row0 + r) * EFF + (c - 2 * HH));
            }
            __half2 hv = __floats2half2_rn(v.x, v.y);
            uint32_t off = SWZ((uint32_t)(r * 128 + kp * 4));
            *(uint32_t*)(sm + SM_AH + off) = *reinterpret_cast<uint32_t*>(&hv);
        }
        {
            const float4* s1 = (const float4*)(wb + ch * 9216);
            float4* d1 = (float4*)(sm + SM_BH);
            for (int i = tid; i < 2304; i += 256) d1[i] = s1[i];
        }
        __syncthreads();
        hmma_chunk(sb + SM_AH, sb + SM_BH, wm, wn, lane, acc);
    }

    hmma_epilogue(acc, row0, wm, wn, lane, bias, Cout, sStat, M, doStat);
    if (doStat) {
        __syncthreads();
        for (int i = tid; i < 2 * HH; i += 256) atomicAdd(&g_stats[i], sStat[i]);
    }
}

// ============================================================================
// Unified GEMM2 (in place, node path): C[M,280] = relu(bn(C)) @ W[280,280] + b
// ============================================================================
__global__ void __launch_bounds__(256, 3)
gemm_inplace_mma(float* __restrict__ C, const uint32_t* __restrict__ wb,
                 const float* __restrict__ bias, int M) {
    extern __shared__ char sm[];
    uint32_t sb = smem_u32(sm);
    const int tid = threadIdx.x, wid = tid >> 5, lane = tid & 31;
    const int wm = wid >> 1, wn = wid & 1;
    const long row0 = (long)blockIdx.x * 64;
    float* sStat = (float*)(sm + SM_STAT);
    float* sSc = (float*)(sm + SM_SC);
    float* sSh = (float*)(sm + SM_SH);

    for (int i = tid; i < 2 * HH; i += 256) sStat[i] = 0.f;
    for (int i = tid; i < HH; i += 256) { sSc[i] = g_scale[i]; sSh[i] = g_shift[i]; }
    float acc[18][4];
#pragma unroll
    for (int nt = 0; nt < 18; nt++)
#pragma unroll
        for (int j = 0; j < 4; j++) acc[nt][j] = 0.f;
    __syncthreads();

    for (int ch = 0; ch < 5; ++ch) {
        if (ch) __syncthreads();
        const int kbase = ch * 64;
        for (int i = tid; i < 2048; i += 256) {
            int r = i >> 5, kp = i & 31;
            int c = kbase + 2 * kp;
            float2 v = make_float2(0.f, 0.f);
            if (c < HH) {
                long row = min(row0 + r, (long)M - 1);
                float2 y = *(const float2*)(C + row * HH + c);
                v.x = fmaxf(fmaf(y.x, sSc[c], sSh[c]), 0.f);
                v.y = fmaxf(fmaf(y.y, sSc[c + 1], sSh[c + 1]), 0.f);
            }
            __half2 hv = __floats2half2_rn(v.x, v.y);
            uint32_t off = SWZ((uint32_t)(r * 128 + kp * 4));
            *(uint32_t*)(sm + SM_AH + off) = *reinterpret_cast<uint32_t*>(&hv);
        }
        {
            const float4* s1 = (const float4*)(wb + ch * 9216);
            float4* d1 = (float4*)(sm + SM_BH);
            for (int i = tid; i < 2304; i += 256) d1[i] = s1[i];
        }
        __syncthreads();
        hmma_chunk(sb + SM_AH, sb + SM_BH, wm, wn, lane, acc);
    }

    hmma_epilogue(acc, row0, wm, wn, lane, bias, C, sStat, M, 1);
    __syncthreads();
    for (int i = tid; i < 2 * HH; i += 256) atomicAdd(&g_stats[i], sStat[i]);
}

// ============================================================================
// combine_f16: m = P1[dst] + P2[src] + ea@W1c (b1 folded into P1).
// Stores m as pre-swizzled fp16 chunk images + fused BN1 stats. 64 edges/block.
// ============================================================================
__global__ void __launch_bounds__(256)
combine_f16(const float* __restrict__ P1, const float* __restrict__ P2,
            const float* __restrict__ ea,
            const int* __restrict__ dst, const int* __restrict__ src,
            const float* __restrict__ W1c, uint32_t* __restrict__ mf) {
    __shared__ float sStat[2 * HH];
    __shared__ float sW[EFF * HH];
    __shared__ int sD[64], sS[64];
    __shared__ float4 sEv[64];
    const int tid = threadIdx.x;
    const long e0 = (long)blockIdx.x * 64;
    uint32_t* mft = mf + (long)blockIdx.x * 5 * 2048;

    for (int i = tid; i < 2 * HH; i += 256) sStat[i] = 0.f;
    for (int i = tid; i < EFF * HH; i += 256) sW[i] = W1c[i];
    if (tid < 64) {
        long e = e0 + tid;
        sD[tid] = dst[e];
        sS[tid] = src[e];
        sEv[tid] = *(const float4*)(ea + e * EFF);
    }
    __syncthreads();

    for (int it = tid; it < 64 * 140; it += 256) {
        int er = it / 140, kp2 = it - er * 140;
        int c = kp2 * 2;
        float2 a = *(const float2*)(P1 + (long)sD[er] * HH + c);
        float2 b = *(const float2*)(P2 + (long)sS[er] * HH + c);
        float4 ev = sEv[er];
        float m0 = a.x + b.x + ev.x * sW[c] + ev.y * sW[HH + c] +
                   ev.z * sW[2 * HH + c] + ev.w * sW[3 * HH + c];
        float m1 = a.y + b.y + ev.x * sW[c + 1] + ev.y * sW[HH + c + 1] +
                   ev.z * sW[2 * HH + c + 1] + ev.w * sW[3 * HH + c + 1];
        atomicAdd(&sStat[c], m0);
        atomicAdd(&sStat[c + 1], m1);
        atomicAdd(&sStat[HH + c], m0 * m0);
        atomicAdd(&sStat[HH + c + 1], m1 * m1);
        __half2 hv = __floats2half2_rn(m0, m1);
        int ch = c >> 6;
        int kpin = (c & 63) >> 1;
        uint32_t off = SWZ((uint32_t)(er * 128 + kpin * 4));
        mft[ch * 2048 + (off >> 2)] = *reinterpret_cast<uint32_t*>(&hv);
    }
    __syncthreads();
    for (int i = tid; i < 2 * HH; i += 256) atomicAdd(&g_stats[i], sStat[i]);
}

// ============================================================================
// gemm2_mf: Y = relu(bn1(m_fp16)) @ W2 + b2, A read from pre-swizzled mf images.
// ============================================================================
__global__ void __launch_bounds__(256, 3)
gemm2_mf(const uint32_t* __restrict__ mf, const uint32_t* __restrict__ wb,
         const float* __restrict__ bias, float* __restrict__ Y) {
    extern __shared__ char sm[];
    uint32_t sb = smem_u32(sm);
    const int tid = threadIdx.x, wid = tid >> 5, lane = tid & 31;
    const int wm = wid >> 1, wn = wid & 1;
    const long row0 = (long)blockIdx.x * 64;
    const uint32_t* mft = mf + (long)blockIdx.x * 5 * 2048;
    float* sStat = (float*)(sm + SM_STAT);
    float* sSc = (float*)(sm + SM_SC);
    float* sSh = (float*)(sm + SM_SH);

    for (int i = tid; i < 2 * HH; i += 256) sStat[i] = 0.f;
    for (int i = tid; i < HH; i += 256) { sSc[i] = g_scale[i]; sSh[i] = g_shift[i]; }
    float acc[18][4];
#pragma unroll
    for (int nt = 0; nt < 18; nt++)
#pragma unroll
        for (int j = 0; j < 4; j++) acc[nt][j] = 0.f;
    __syncthreads();

    for (int ch = 0; ch < 5; ++ch) {
        if (ch) __syncthreads();
        // ---- A-stage: linear copy of pre-swizzled image, bn+relu per element ----
        for (int i = tid; i < 2048; i += 256) {
            uint32_t u = mft[ch * 2048 + i];
            uint32_t orig = SWZ((uint32_t)(i * 4));       // involutive -> unswizzled offset
            int kpin = (orig & 127) >> 2;
            int c = ch * 64 + 2 * kpin;
            __half2 hval = *reinterpret_cast<__half2*>(&u);
            float2 v = __half22float2(hval);
            float w0 = (c < HH) ? fmaxf(fmaf(v.x, sSc[c], sSh[c]), 0.f) : 0.f;
            float w1 = (c + 1 < HH) ? fmaxf(fmaf(v.y, sSc[c + 1], sSh[c + 1]), 0.f) : 0.f;
            __half2 hv = __floats2half2_rn(w0, w1);
            *(uint32_t*)(sm + SM_AH + i * 4) = *reinterpret_cast<uint32_t*>(&hv);
        }
        {
            const float4* s1 = (const float4*)(wb + ch * 9216);
            float4* d1 = (float4*)(sm + SM_BH);
            for (int i = tid; i < 2304; i += 256) d1[i] = s1[i];
        }
        __syncthreads();
        hmma_chunk(sb + SM_AH, sb + SM_BH, wm, wn, lane, acc);
    }

    hmma_epilogue(acc, row0, wm, wn, lane, bias, Y, sStat, EE, 1);
    __syncthreads();
    for (int i = tid; i < 2 * HH; i += 256) atomicAdd(&g_stats[i], sStat[i]);
}

// ---------------- finalize BN stats -> scale/shift; self-zero ----------------
__global__ void finalize_stats(const float* __restrict__ g, const float* __restrict__ be,
                               float invM) {
    int c = threadIdx.x;
    if (c >= HH) return;
    float s = g_stats[c];
    float s2 = g_stats[HH + c];
    g_stats[c] = 0.f;
    g_stats[HH + c] = 0.f;
    float mean = s * invM;
    float var = s2 * invM - mean * mean;
    float rstd = rsqrtf(var + 1e-5f);
    float sc = g[c] * rstd;
    g_scale[c] = sc;
    g_shift[c] = fmaf(-mean, sc, be[c]);
}

// ---------------- scatter: agg[dst[e]] += relu(bn(Y[e])) ----------------
__global__ void scatter_bn_relu(const float* __restrict__ Y, const int* __restrict__ dst,
                                float* __restrict__ agg) {
    long i = (long)blockIdx.x * 256 + threadIdx.x;
    if (i >= (long)EE * (HH / 4)) return;
    int e = (int)(i / (HH / 4));
    int c = (int)(i - (long)e * (HH / 4)) * 4;
    float4 y = *reinterpret_cast<const float4*>(Y + (long)e * HH + c);
    float* p = agg + (long)dst[e] * HH + c;
    float v0 = fmaf(y.x, g_scale[c + 0], g_shift[c + 0]);
    float v1 = fmaf(y.y, g_scale[c + 1], g_shift[c + 1]);
    float v2 = fmaf(y.z, g_scale[c + 2], g_shift[c + 2]);
    float v3 = fmaf(y.w, g_scale[c + 3], g_shift[c + 3]);
    if (v0 > 0.f) atomicAdd(p + 0, v0);
    if (v1 > 0.f) atomicAdd(p + 1, v1);
    if (v2 > 0.f) atomicAdd(p + 2, v2);
    if (v3 > 0.f) atomicAdd(p + 3, v3);
}

// ---------------- residual: h += relu(bn(U)) ----------------
__global__ void residual_bn_relu(const float* __restrict__ U, float* __restrict__ h) {
    int i = blockIdx.x * 256 + threadIdx.x;
    if (i >= NN * HH / 4) return;
    int c = (i % (HH / 4)) * 4;
    float4 u = *reinterpret_cast<const float4*>(U + (long)i * 4);
    float4 hv = *reinterpret_cast<float4*>(h + (long)i * 4);
    hv.x += fmaxf(fmaf(u.x, g_scale[c + 0], g_shift[c + 0]), 0.f);
    hv.y += fmaxf(fmaf(u.y, g_scale[c + 1], g_shift[c + 1]), 0.f);
    hv.z += fmaxf(fmaf(u.z, g_scale[c + 2], g_shift[c + 2]), 0.f);
    hv.w += fmaxf(fmaf(u.w, g_scale[c + 3], g_shift[c + 3]), 0.f);
    *reinterpret_cast<float4*>(h + (long)i * 4) = hv;
}

// ---------------- pooling + head ----------------
__global__ void pool_accum(const float* __restrict__ h, const int* __restrict__ batch,
                           float* __restrict__ pool) {
    int i = blockIdx.x * 256 + threadIdx.x;
    if (i >= NN * HH / 4) return;
    int n = i / (HH / 4);
    int c = (i - n * (HH / 4)) * 4;
    float4 v = *reinterpret_cast<const float4*>(h + (long)i * 4);
    float* p = pool + (long)batch[n] * HH + c;
    atomicAdd(p + 0, v.x);
    atomicAdd(p + 1, v.y);
    atomicAdd(p + 2, v.z);
    atomicAdd(p + 3, v.w);
}

__global__ void pool_count(const int* __restrict__ batch, float* __restrict__ cnt) {
    int n = blockIdx.x * 256 + threadIdx.x;
    if (n < NN) atomicAdd(&cnt[batch[n]], 1.0f);
}

__global__ void head_kernel(const float* __restrict__ pool, const float* __restrict__ cnt,
                            const float* __restrict__ Wmu, const float* __restrict__ bmu,
                            float* __restrict__ out) {
    int gph = blockIdx.x;
    int z = threadIdx.x;
    float inv = 1.0f / fmaxf(cnt[gph], 1.0f);
    float s = bmu[z];
    for (int k = 0; k < HH; k++) s = fmaf(pool[gph * HH + k] * inv, Wmu[k * ZZ + z], s);
    out[gph * ZZ + z] = s;
}

// ---------------- host orchestration ----------------
extern "C" void kernel_launch(void* const* d_in, const int* in_sizes, int n_in,
                              void* d_out, int out_size) {
    const float *x, *edge_attr, *Wi, *bi, *Wm1, *bm1, *g1, *be1, *Wm2, *bm2, *g2, *be2;
    const float *Wu1, *bu1, *g3, *be3, *Wu2, *bu2, *g4, *be4, *Wmu, *bmu;
    const int *edge_index, *batch;

    if (in_sizes[2] == 2 * EE) {
        x = (const float*)d_in[0];   edge_attr = (const float*)d_in[1];
        edge_index = (const int*)d_in[2]; batch = (const int*)d_in[3];
        Wi = (const float*)d_in[4];  bi = (const float*)d_in[5];
        Wm1 = (const float*)d_in[6]; bm1 = (const float*)d_in[7];
        g1 = (const float*)d_in[8];  be1 = (const float*)d_in[9];
        Wm2 = (const float*)d_in[10]; bm2 = (const float*)d_in[11];
        g2 = (const float*)d_in[12]; be2 = (const float*)d_in[13];
        Wu1 = (const float*)d_in[14]; bu1 = (const float*)d_in[15];
        g3 = (const float*)d_in[16]; be3 = (const float*)d_in[17];
        Wu2 = (const float*)d_in[18]; bu2 = (const float*)d_in[19];
        g4 = (const float*)d_in[20]; be4 = (const float*)d_in[21];
        Wmu = (const float*)d_in[22]; bmu = (const float*)d_in[23];
    } else {
        x = (const float*)d_in[0];   edge_attr = (const float*)d_in[1];
        Wi = (const float*)d_in[2];  bi = (const float*)d_in[3];
        Wm1 = (const float*)d_in[4]; bm1 = (const float*)d_in[5];
        g1 = (const float*)d_in[6];  be1 = (const float*)d_in[7];
        Wm2 = (const float*)d_in[8]; bm2 = (const float*)d_in[9];
        g2 = (const float*)d_in[10]; be2 = (const float*)d_in[11];
        Wu1 = (const float*)d_in[12]; bu1 = (const float*)d_in[13];
        g3 = (const float*)d_in[14]; be3 = (const float*)d_in[15];
        Wu2 = (const float*)d_in[16]; bu2 = (const float*)d_in[17];
        g4 = (const float*)d_in[18]; be4 = (const float*)d_in[19];
        Wmu = (const float*)d_in[20]; bmu = (const float*)d_in[21];
        edge_index = (const int*)d_in[22]; batch = (const int*)d_in[23];
    }
    const int* src = edge_index;
    const int* dst = edge_index + EE;

    float *hbuf, *Ybuf, *aggbuf, *Ubuf, *poolbuf, *cntbuf, *statsbuf, *zbuf;
    uint32_t *wb, *mfbuf;
    cudaGetSymbolAddress((void**)&hbuf, g_h);
    cudaGetSymbolAddress((void**)&Ybuf, g_Y);
    cudaGetSymbolAddress((void**)&aggbuf, g_agg);
    cudaGetSymbolAddress((void**)&Ubuf, g_U);
    cudaGetSymbolAddress((void**)&poolbuf, g_pool);
    cudaGetSymbolAddress((void**)&cntbuf, g_cnt);
    cudaGetSymbolAddress((void**)&statsbuf, g_stats);
    cudaGetSymbolAddress((void**)&zbuf, g_zb);
    cudaGetSymbolAddress((void**)&wb, g_wb);
    cudaGetSymbolAddress((void**)&mfbuf, g_mf);

    cudaFuncSetAttribute(gemm_cat_mma, cudaFuncAttributeMaxDynamicSharedMemorySize, SM_TOT);
    cudaFuncSetAttribute(gemm_inplace_mma, cudaFuncAttributeMaxDynamicSharedMemorySize, SM_TOT);
    cudaFuncSetAttribute(gemm2_mf, cudaFuncAttributeMaxDynamicSharedMemorySize, SM_TOT);

    const int NH_BLKS = (NN * HH + 255) / 256;
    const int NH4_BLKS = (NN * HH / 4 + 255) / 256;
    const int UPD_BLKS = (NN + 63) / 64;              // 313
    const long EH4 = (long)EE * (HH / 4);
    const int SC_BLKS = (int)((EH4 + 255) / 256);

    zero4_kernel<<<1, 256>>>((float4*)statsbuf, 2 * HH / 4);
    zero4_kernel<<<1, 256>>>((float4*)zbuf, HH / 4);
    input_layer<<<NH_BLKS, 256>>>(x, Wi, bi, hbuf);

    // ---- pre-convert ALL weight images ----
    for (int l = 0; l < LL; l++) {
        uint32_t* base = wb + (long)l * 29 * 9216;
        const float* wm1 = Wm1 + (long)l * K_MSG * HH;
        conv_w<<<(5 * 9216) / 256, 256>>>(wm1, HH, 5, base);                       // W1a
        conv_w<<<(5 * 9216) / 256, 256>>>(wm1 + 280 * HH, HH, 5, base + 5 * 9216); // W1b
        conv_w<<<(5 * 9216) / 256, 256>>>(Wm2 + (long)l * HH * HH, HH, 5, base + 10 * 9216);
        conv_w<<<(9 * 9216) / 256, 256>>>(Wu1 + (long)l * K_UPD * HH, K_UPD, 9, base + 15 * 9216);
        conv_w<<<(5 * 9216) / 256, 256>>>(Wu2 + (long)l * HH * HH, HH, 5, base + 24 * 9216);
    }

    for (int l = 0; l < LL; l++) {
        uint32_t* wbase = wb + (long)l * 29 * 9216;
        const float* wm1 = Wm1 + (long)l * K_MSG * HH;
        const float* w1c = wm1 + 560 * HH;

        // ---- message MLP: P1=h@W1a+b1, P2=h@W1b, combine -> mf, GEMM2 ----
        gemm_cat_mma<<<UPD_BLKS, 256, SM_TOT>>>(hbuf, nullptr, hbuf, nullptr, nullptr,
                                                wbase, bm1 + l * HH, Ubuf /*P1*/, NN, HH, 5, 0);
        gemm_cat_mma<<<UPD_BLKS, 256, SM_TOT>>>(hbuf, nullptr, hbuf, nullptr, nullptr,
                                                wbase + 5 * 9216, zbuf, aggbuf /*P2*/, NN, HH, 5, 0);
        combine_f16<<<ETILES, 256>>>(Ubuf, aggbuf, edge_attr, dst, src, w1c, mfbuf);
        finalize_stats<<<1, 288>>>(g1 + l * HH, be1 + l * HH, 1.0f / EE);
        gemm2_mf<<<ETILES, 256, SM_TOT>>>(mfbuf, wbase + 10 * 9216, bm2 + l * HH, Ybuf);
        finalize_stats<<<1, 288>>>(g2 + l * HH, be2 + l * HH, 1.0f / EE);

        // ---- aggregate ----
        zero4_kernel<<<NH4_BLKS, 256>>>((float4*)aggbuf, NN * HH / 4);
        scatter_bn_relu<<<SC_BLKS, 256>>>(Ybuf, dst, aggbuf);

        // ---- update MLP on nodes ----
        gemm_cat_mma<<<UPD_BLKS, 256, SM_TOT>>>(hbuf, nullptr, aggbuf, nullptr, nullptr,
                                                wbase + 15 * 9216, bu1 + l * HH, Ubuf, NN, K_UPD, 9, 1);
        finalize_stats<<<1, 288>>>(g3 + l * HH, be3 + l * HH, 1.0f / NN);
        gemm_inplace_mma<<<UPD_BLKS, 256, SM_TOT>>>(Ubuf, wbase + 24 * 9216, bu2 + l * HH, NN);
        finalize_stats<<<1, 288>>>(g4 + l * HH, be4 + l * HH, 1.0f / NN);
        residual_bn_relu<<<NH4_BLKS, 256>>>(Ubuf, hbuf);
    }

    zero4_kernel<<<(GG * HH / 4 + 255) / 256, 256>>>((float4*)poolbuf, GG * HH / 4);
    zero4_kernel<<<1, 256>>>((float4*)cntbuf, GG / 4);
    pool_accum<<<NH4_BLKS, 256>>>(hbuf, batch, poolbuf);
    pool_count<<<(NN + 255) / 256, 256>>>(batch, cntbuf);
    head_kernel<<<GG, ZZ>>>(poolbuf, cntbuf, Wmu, bmu, (float*)d_out);
}